// round 11
// baseline (speedup 1.0000x reference)
#include <cuda_runtime.h>
#include <cuda_bf16.h>
#include <cstdint>

#define THREADS 128
#define NWARP 4
#define TILES_PER_WARP 2
#define NCOEF 1001
#define FULLMASK 0xffffffffu

__device__ __forceinline__ uint32_t cvta_s(const void* p) {
    return (uint32_t)__cvta_generic_to_shared(p);
}
__device__ __forceinline__ void ldm_x2(uint32_t& r0, uint32_t& r1, uint32_t addr) {
    asm volatile("ldmatrix.sync.aligned.m8n8.x2.shared.b16 {%0,%1}, [%2];"
                 : "=r"(r0), "=r"(r1) : "r"(addr));
}
__device__ __forceinline__ void mma16816(float* d, const uint32_t* a,
                                         const uint32_t* b) {
    asm volatile("mma.sync.aligned.m16n8k16.row.col.f32.bf16.bf16.f32 "
                 "{%0,%1,%2,%3}, {%4,%5,%6,%7}, {%8,%9}, {%0,%1,%2,%3};"
                 : "+f"(d[0]), "+f"(d[1]), "+f"(d[2]), "+f"(d[3])
                 : "r"(a[0]), "r"(a[1]), "r"(a[2]), "r"(a[3]),
                   "r"(b[0]), "r"(b[1]));
}
__device__ __forceinline__ void mma16816_z(float* d, const uint32_t* a,
                                           const uint32_t* b) {
    asm volatile("mma.sync.aligned.m16n8k16.row.col.f32.bf16.bf16.f32 "
                 "{%0,%1,%2,%3}, {%4,%5,%6,%7}, {%8,%9}, {%10,%10,%10,%10};"
                 : "=f"(d[0]), "=f"(d[1]), "=f"(d[2]), "=f"(d[3])
                 : "r"(a[0]), "r"(a[1]), "r"(a[2]), "r"(a[3]),
                   "r"(b[0]), "r"(b[1]), "f"(0.0f));
}

// For one element value xe and this thread's cL: the 4 packed bf16x2 pairs at
// exponents (2cL+off, 2cL+1+off), off = 0,8,16,24 — hi part and lo residual.
// cvt output low half = even exponent (first k of the pair), matching the
// m16n8k16 A-fragment register layout.
__device__ __forceinline__ void frag_powers(float xe, int cL,
                                            uint32_t hi[4], uint32_t lo[4]) {
    float x2 = xe * xe, x4 = x2 * x2, x8 = x4 * x4;
    float x16 = x8 * x8, x24 = x16 * x8;
    float b = (cL == 0) ? 1.0f : (cL == 1) ? x2 : (cL == 2) ? x4 : x4 * x2;
    float p0 = b, p1 = b * xe;
    float ev[4] = {p0, p0 * x8, p0 * x16, p0 * x24};
    float od[4] = {p1, p1 * x8, p1 * x16, p1 * x24};
    #pragma unroll
    for (int j = 0; j < 4; j++) {
        __nv_bfloat162 h2 = __floats2bfloat162_rn(ev[j], od[j]);  // low = even
        uint32_t hb = *reinterpret_cast<uint32_t*>(&h2);
        float f0 = __uint_as_float(hb << 16);
        float f1 = __uint_as_float(hb & 0xFFFF0000u);
        __nv_bfloat162 l2 = __floats2bfloat162_rn(ev[j] - f0, od[j] - f1);
        hi[j] = hb;
        lo[j] = *reinterpret_cast<uint32_t*>(&l2);
    }
}

__device__ __forceinline__ float horner8(float4 a, float4 b, float q) {
    float h = b.w;
    h = fmaf(h, q, b.z); h = fmaf(h, q, b.y); h = fmaf(h, q, b.x);
    h = fmaf(h, q, a.w); h = fmaf(h, q, a.z); h = fmaf(h, q, a.y);
    return fmaf(h, q, a.x);
}

__global__ __launch_bounds__(THREADS)
void poly_tc_kernel(const float* __restrict__ xg,
                    const float* __restrict__ wg,
                    float* __restrict__ out) {
    __shared__ __align__(128) unsigned char smW[32 * 128];
    __shared__ __align__(128) unsigned char smS[NWARP][32 * 128];  // S round-trip

    const int tid  = threadIdx.x;
    const int wid  = tid >> 5;
    const int lane = tid & 31;
    const int g    = lane >> 2;   // mma groupID
    const int cL   = lane & 3;    // mma thread-in-group

    const int warp_base = blockIdx.x * (NWARP * TILES_PER_WARP * 32)
                        + wid * (TILES_PER_WARP * 32);
    float x0 = xg[warp_base + lane];
    float x1 = xg[warp_base + 32 + lane];

    // ---- W_hi / W_lo tiles in smem (once per block), 128B swizzled rows ----
    for (int i = tid; i < 1024; i += THREADS) {
        float v = (i < NCOEF) ? wg[i] : 0.0f;
        __nv_bfloat16 hb = __float2bfloat16_rn(v);
        __nv_bfloat16 lb = __float2bfloat16_rn(v - __bfloat162float(hb));
        int n = i >> 5, k = i & 31;
        int ch = k >> 3, byo = (k & 7) * 2;
        *(__nv_bfloat16*)(smW + n * 128 + ((ch ^ (n & 7)) & 7) * 16 + byo) = hb;
        *(__nv_bfloat16*)(smW + n * 128 + (((ch + 4) ^ (n & 7)) & 7) * 16 + byo) = lb;
    }
    __syncthreads();

    // ---- persistent B fragments: bf[part][t][h][2] ----
    uint32_t bf[2][4][2][2];
    {
        const uint32_t wbase = cvta_s(smW);
        const int lr = lane & 15;
        #pragma unroll
        for (int part = 0; part < 2; part++)
            #pragma unroll
            for (int t = 0; t < 4; t++)
                #pragma unroll
                for (int h = 0; h < 2; h++) {
                    int row = 8 * t + (lr & 7);
                    int ch  = part * 4 + 2 * h + (lr >> 3);
                    uint32_t addr = wbase + row * 128 + ((ch ^ (row & 7)) & 7) * 16;
                    ldm_x2(bf[part][t][h][0], bf[part][t][h][1], addr);
                }
    }

    const uint32_t sbase = cvta_s(smS[wid]);

    #pragma unroll
    for (int tile = 0; tile < TILES_PER_WARP; tile++) {
        const float xt = tile ? x1 : x0;
        // q = x^32 for own element (epilogue)
        float t2 = xt * xt, t4 = t2 * t2, t8 = t4 * t4, t16 = t8 * t8;
        const float q = t16 * t16;

        __syncwarp();   // prior tile's S readback done before overwriting smS

        #pragma unroll
        for (int m = 0; m < 2; m++) {
            // x of the two rows this thread covers in the A fragment
            float xe0 = __shfl_sync(FULLMASK, xt, 16 * m + g);
            float xe1 = __shfl_sync(FULLMASK, xt, 16 * m + g + 8);

            // Build A fragments directly in registers (no smem, no ldmatrix)
            uint32_t h0[4], l0[4], h1[4], l1[4];
            frag_powers(xe0, cL, h0, l0);
            frag_powers(xe1, cL, h1, l1);
            // A[part][h][4]: reg0=row g, reg1=row g+8 (k-lo); reg2,3 = k-hi
            uint32_t A[2][2][4] = {
                { {h0[0], h1[0], h0[1], h1[1]}, {h0[2], h1[2], h0[3], h1[3]} },
                { {l0[0], l1[0], l0[1], l1[1]}, {l0[2], l1[2], l0[3], l1[3]} } };

            float D[4][4];
            #pragma unroll
            for (int t = 0; t < 4; t++) {
                mma16816_z(D[t], A[0][0], bf[0][t][0]);  // p_hi k0  x w_hi
                mma16816 (D[t], A[0][1], bf[0][t][1]);   // p_hi k16 x w_hi
                mma16816 (D[t], A[1][0], bf[0][t][0]);   // p_lo k0  x w_hi
                mma16816 (D[t], A[1][1], bf[0][t][1]);   // p_lo k16 x w_hi
                mma16816 (D[t], A[0][0], bf[1][t][0]);   // p_hi k0  x w_lo
                mma16816 (D[t], A[0][1], bf[1][t][1]);   // p_hi k16 x w_lo
            }

            // Scatter S_j to smS (swizzled fp32 rows; row = element, col = j)
            #pragma unroll
            for (int t = 0; t < 4; t++) {
                int ch  = 2 * t + (cL >> 1);
                int sub = 8 * (cL & 1);
                int r0  = 16 * m + g;
                int r1  = r0 + 8;
                uint32_t a0 = sbase + r0 * 128 + ((ch ^ (r0 & 7)) & 7) * 16 + sub;
                uint32_t a1 = sbase + r1 * 128 + ((ch ^ (r1 & 7)) & 7) * 16 + sub;
                asm volatile("st.shared.v2.b32 [%0], {%1,%2};"
                             :: "r"(a0), "f"(D[t][0]), "f"(D[t][1]));
                asm volatile("st.shared.v2.b32 [%0], {%1,%2};"
                             :: "r"(a1), "f"(D[t][2]), "f"(D[t][3]));
            }
        }
        __syncwarp();   // S complete before readback

        // Lane reads its own element's 32 S values, Horner in q = x^32
        float4 s[8];
        #pragma unroll
        for (int ch = 0; ch < 8; ch++) {
            uint32_t addr = sbase + lane * 128 + ((ch ^ (lane & 7)) & 7) * 16;
            asm volatile("ld.shared.v4.f32 {%0,%1,%2,%3}, [%4];"
                         : "=f"(s[ch].x), "=f"(s[ch].y),
                           "=f"(s[ch].z), "=f"(s[ch].w) : "r"(addr));
        }
        float q2 = q * q, q4 = q2 * q2, q8 = q4 * q4;
        float C0 = horner8(s[0], s[1], q);
        float C1 = horner8(s[2], s[3], q);
        float C2 = horner8(s[4], s[5], q);
        float C3 = horner8(s[6], s[7], q);
        float y = fmaf(fmaf(fmaf(C3, q8, C2), q8, C1), q8, C0);
        out[warp_base + tile * 32 + lane] = y;
    }
}

extern "C" void kernel_launch(void* const* d_in, const int* in_sizes, int n_in,
                              void* d_out, int out_size) {
    const float* x = (const float*)d_in[0];   // (512, 1024) fp32
    const float* w = (const float*)d_in[1];   // (1001,) fp32
    float* out = (float*)d_out;

    const int grid = out_size / (NWARP * TILES_PER_WARP * 32);   // 2048
    poly_tc_kernel<<<grid, THREADS>>>(x, w, out);
}

// round 12
// speedup vs baseline: 1.1111x; 1.1111x over previous
#include <cuda_runtime.h>
#include <cuda_bf16.h>
#include <cstdint>

#define THREADS 128
#define NWARP 4
#define NCOEF 1001
#define FULLMASK 0xffffffffu
#define NSM 148
#define BLOCKS_PER_SM 5

__device__ __forceinline__ uint32_t cvta_s(const void* p) {
    return (uint32_t)__cvta_generic_to_shared(p);
}
__device__ __forceinline__ void ldm_x2(uint32_t& r0, uint32_t& r1, uint32_t addr) {
    asm volatile("ldmatrix.sync.aligned.m8n8.x2.shared.b16 {%0,%1}, [%2];"
                 : "=r"(r0), "=r"(r1) : "r"(addr));
}
__device__ __forceinline__ void mma16816(float* d, const uint32_t* a,
                                         const uint32_t* b) {
    asm volatile("mma.sync.aligned.m16n8k16.row.col.f32.bf16.bf16.f32 "
                 "{%0,%1,%2,%3}, {%4,%5,%6,%7}, {%8,%9}, {%0,%1,%2,%3};"
                 : "+f"(d[0]), "+f"(d[1]), "+f"(d[2]), "+f"(d[3])
                 : "r"(a[0]), "r"(a[1]), "r"(a[2]), "r"(a[3]),
                   "r"(b[0]), "r"(b[1]));
}
__device__ __forceinline__ void mma16816_z(float* d, const uint32_t* a,
                                           const uint32_t* b) {
    asm volatile("mma.sync.aligned.m16n8k16.row.col.f32.bf16.bf16.f32 "
                 "{%0,%1,%2,%3}, {%4,%5,%6,%7}, {%8,%9}, {%10,%10,%10,%10};"
                 : "=f"(d[0]), "=f"(d[1]), "=f"(d[2]), "=f"(d[3])
                 : "r"(a[0]), "r"(a[1]), "r"(a[2]), "r"(a[3]),
                   "r"(b[0]), "r"(b[1]), "f"(0.0f));
}

// Packed bf16x2 A-fragment pairs at exponents (2cL+off, 2cL+1+off),
// off = 0,8,16,24; hi part and lo residual. cvt low half = even exponent.
__device__ __forceinline__ void frag_powers(float xe, int cL,
                                            uint32_t hi[4], uint32_t lo[4]) {
    float x2 = xe * xe, x4 = x2 * x2, x8 = x4 * x4;
    float x16 = x8 * x8, x24 = x16 * x8;
    float b = (cL == 0) ? 1.0f : (cL == 1) ? x2 : (cL == 2) ? x4 : x4 * x2;
    float p0 = b, p1 = b * xe;
    float ev[4] = {p0, p0 * x8, p0 * x16, p0 * x24};
    float od[4] = {p1, p1 * x8, p1 * x16, p1 * x24};
    #pragma unroll
    for (int j = 0; j < 4; j++) {
        __nv_bfloat162 h2 = __floats2bfloat162_rn(ev[j], od[j]);
        uint32_t hb = *reinterpret_cast<uint32_t*>(&h2);
        float f0 = __uint_as_float(hb << 16);
        float f1 = __uint_as_float(hb & 0xFFFF0000u);
        __nv_bfloat162 l2 = __floats2bfloat162_rn(ev[j] - f0, od[j] - f1);
        hi[j] = hb;
        lo[j] = *reinterpret_cast<uint32_t*>(&l2);
    }
}

__device__ __forceinline__ float horner8(float4 a, float4 b, float q) {
    float h = b.w;
    h = fmaf(h, q, b.z); h = fmaf(h, q, b.y); h = fmaf(h, q, b.x);
    h = fmaf(h, q, a.w); h = fmaf(h, q, a.z); h = fmaf(h, q, a.y);
    return fmaf(h, q, a.x);
}

__global__ __launch_bounds__(THREADS)
void poly_tc_kernel(const float* __restrict__ xg,
                    const float* __restrict__ wg,
                    float* __restrict__ out,
                    int ntiles) {
    __shared__ __align__(128) unsigned char smW[32 * 128];
    __shared__ __align__(128) unsigned char smS[NWARP][32 * 128];

    const int tid  = threadIdx.x;
    const int wid  = tid >> 5;
    const int lane = tid & 31;
    const int g    = lane >> 2;
    const int cL   = lane & 3;

    // ---- prologue (once per persistent block) ----
    for (int i = tid; i < 1024; i += THREADS) {
        float v = (i < NCOEF) ? wg[i] : 0.0f;
        __nv_bfloat16 hb = __float2bfloat16_rn(v);
        __nv_bfloat16 lb = __float2bfloat16_rn(v - __bfloat162float(hb));
        int n = i >> 5, k = i & 31;
        int ch = k >> 3, byo = (k & 7) * 2;
        *(__nv_bfloat16*)(smW + n * 128 + ((ch ^ (n & 7)) & 7) * 16 + byo) = hb;
        *(__nv_bfloat16*)(smW + n * 128 + (((ch + 4) ^ (n & 7)) & 7) * 16 + byo) = lb;
    }
    __syncthreads();

    uint32_t bf[2][4][2][2];   // persistent B fragments [part][t][h][2]
    {
        const uint32_t wbase = cvta_s(smW);
        const int lr = lane & 15;
        #pragma unroll
        for (int part = 0; part < 2; part++)
            #pragma unroll
            for (int t = 0; t < 4; t++)
                #pragma unroll
                for (int h = 0; h < 2; h++) {
                    int row = 8 * t + (lr & 7);
                    int ch  = part * 4 + 2 * h + (lr >> 3);
                    uint32_t addr = wbase + row * 128 + ((ch ^ (row & 7)) & 7) * 16;
                    ldm_x2(bf[part][t][h][0], bf[part][t][h][1], addr);
                }
    }

    const uint32_t sbase = cvta_s(smS[wid]);
    const int warp_gid = blockIdx.x * NWARP + wid;
    const int stride   = gridDim.x * NWARP;

    float x_cur = (warp_gid < ntiles) ? xg[warp_gid * 32 + lane] : 0.0f;

    #pragma unroll 1
    for (int tile = warp_gid; tile < ntiles; tile += stride) {
        // prefetch next tile's x behind this tile's compute
        const int nt = tile + stride;
        float x_nxt = (nt < ntiles) ? xg[nt * 32 + lane] : 0.0f;

        const float xt = x_cur;
        float t2 = xt * xt, t4 = t2 * t2, t8 = t4 * t4, t16 = t8 * t8;
        const float q = t16 * t16;   // x^32, own element

        __syncwarp();   // prior tile's S readback done before overwrite

        #pragma unroll
        for (int m = 0; m < 2; m++) {
            float xe0 = __shfl_sync(FULLMASK, xt, 16 * m + g);
            float xe1 = __shfl_sync(FULLMASK, xt, 16 * m + g + 8);

            uint32_t h0[4], l0[4], h1[4], l1[4];
            frag_powers(xe0, cL, h0, l0);
            frag_powers(xe1, cL, h1, l1);
            uint32_t A[2][2][4] = {
                { {h0[0], h1[0], h0[1], h1[1]}, {h0[2], h1[2], h0[3], h1[3]} },
                { {l0[0], l1[0], l0[1], l1[1]}, {l0[2], l1[2], l0[3], l1[3]} } };

            float D[4][4];
            #pragma unroll
            for (int t = 0; t < 4; t++) {
                mma16816_z(D[t], A[0][0], bf[0][t][0]);
                mma16816 (D[t], A[0][1], bf[0][t][1]);
                mma16816 (D[t], A[1][0], bf[0][t][0]);
                mma16816 (D[t], A[1][1], bf[0][t][1]);
                mma16816 (D[t], A[0][0], bf[1][t][0]);
                mma16816 (D[t], A[0][1], bf[1][t][1]);
            }

            #pragma unroll
            for (int t = 0; t < 4; t++) {
                int ch  = 2 * t + (cL >> 1);
                int sub = 8 * (cL & 1);
                int r0  = 16 * m + g;
                int r1  = r0 + 8;
                uint32_t a0 = sbase + r0 * 128 + ((ch ^ (r0 & 7)) & 7) * 16 + sub;
                uint32_t a1 = sbase + r1 * 128 + ((ch ^ (r1 & 7)) & 7) * 16 + sub;
                asm volatile("st.shared.v2.b32 [%0], {%1,%2};"
                             :: "r"(a0), "f"(D[t][0]), "f"(D[t][1]));
                asm volatile("st.shared.v2.b32 [%0], {%1,%2};"
                             :: "r"(a1), "f"(D[t][2]), "f"(D[t][3]));
            }
        }
        __syncwarp();   // S complete before readback

        float4 s[8];
        #pragma unroll
        for (int ch = 0; ch < 8; ch++) {
            uint32_t addr = sbase + lane * 128 + ((ch ^ (lane & 7)) & 7) * 16;
            asm volatile("ld.shared.v4.f32 {%0,%1,%2,%3}, [%4];"
                         : "=f"(s[ch].x), "=f"(s[ch].y),
                           "=f"(s[ch].z), "=f"(s[ch].w) : "r"(addr));
        }
        float q2 = q * q, q4 = q2 * q2, q8 = q4 * q4;
        float C0 = horner8(s[0], s[1], q);
        float C1 = horner8(s[2], s[3], q);
        float C2 = horner8(s[4], s[5], q);
        float C3 = horner8(s[6], s[7], q);
        float y = fmaf(fmaf(fmaf(C3, q8, C2), q8, C1), q8, C0);
        out[tile * 32 + lane] = y;

        x_cur = x_nxt;
    }
}

extern "C" void kernel_launch(void* const* d_in, const int* in_sizes, int n_in,
                              void* d_out, int out_size) {
    const float* x = (const float*)d_in[0];   // (512, 1024) fp32
    const float* w = (const float*)d_in[1];   // (1001,) fp32
    float* out = (float*)d_out;

    const int ntiles = out_size / 32;              // 16384 warp-tiles
    const int grid = NSM * BLOCKS_PER_SM;          // 740 persistent blocks
    poly_tc_kernel<<<grid, THREADS>>>(x, w, out, ntiles);
}